// round 7
// baseline (speedup 1.0000x reference)
#include <cuda_runtime.h>
#include <cuda_bf16.h>

// Problem constants
#define Bz 4
#define Nz 128
#define Mz 128
#define Dz 256
#define BDz 1024

#define KSPLIT 4
#define TSZ (Bz * Nz * Dz)      // 131072 elems (T)
#define SSZ (Bz * Nz * Mz)      // 65536 elems (S)

// Scratch in device globals (no allocation allowed).
__device__ float g_Aw[Dz * Dz];                // Aw[d][e] = sum_k A[d,e,k]*W[k]
__device__ float g_Tp[KSPLIT * TSZ];           // T partials, split over d
__device__ float g_Sp[KSPLIT * SSZ];           // S partials, split over e
__device__ int   g_cnt2[32];                   // k2-tile completion: [rtile(8)][echunk(4)]
__device__ int   g_cnt3[16];                   // k3 split-K epilogue tickets

// ---------------------------------------------------------------------------
// Kernel 1 (round-2 proven version): Aw[row] = dot(A[row,:1024], W)
// One warp per row; W in smem; float4 loads. HBM-bound: 268 MB streamed.
// Block 0 additionally resets the k23 counters (k1 precedes k23 on stream).
// ---------------------------------------------------------------------------
__global__ __launch_bounds__(256) void k1_reduce_A(const float* __restrict__ A,
                                                   const float* __restrict__ W) {
    __shared__ float4 sW[BDz / 4];
    int tid = threadIdx.x;
    if (blockIdx.x == 0) {
        if (tid < 32) g_cnt2[tid] = 0;
        if (tid < 16) g_cnt3[tid] = 0;
    }
    sW[tid] = reinterpret_cast<const float4*>(W)[tid];
    __syncthreads();

    int warp = tid >> 5;
    int lane = tid & 31;
    long row = (long)blockIdx.x * 8 + warp;
    const float4* Arow = reinterpret_cast<const float4*>(A) + row * (BDz / 4);

    float acc = 0.0f;
#pragma unroll
    for (int i = 0; i < 8; i++) {
        float4 a = Arow[i * 32 + lane];
        float4 w = sW[i * 32 + lane];
        acc += a.x * w.x + a.y * w.y + a.z * w.z + a.w * w.w;
    }
#pragma unroll
    for (int off = 16; off; off >>= 1)
        acc += __shfl_xor_sync(0xffffffffu, acc, off);
    if (lane == 0) g_Aw[row] = acc;
}

// ---------------------------------------------------------------------------
// Kernel 23: fused k2 + k3 in one launch, 192 blocks.
//   blocks [0,128):   k2 tile (etile 4 x rtile 8 x ks 4):
//                     Tp[ks][r,e] = sum_{d in chunk ks} X[r,d]*Aw[d,e]
//                     then release counter g_cnt2[rtile*4 + etile] (target 4:
//                     the 4 d-chunks of the same (rtile, e-chunk)).
//   blocks [128,192): k3 tile (mt 2 x nt 2 x b 4 x ks 4): spin on
//                     g_cnt2[(b*2+nt)*4 + ks] == 4, then
//                     Sp[ks] = T(n, e-chunk ks) @ Y(m, e-chunk ks)^T,
//                     last of the 4 ks blocks per tile sums Sp + bias -> S.
// Deadlock-safe: all 128 producers have the lowest block IDs -> scheduled in
// wave 1 (148 SMs), never wait, exit and free slots for late consumers.
// ---------------------------------------------------------------------------
__global__ __launch_bounds__(256) void k23_fused(const float* __restrict__ X,
                                                 const float* __restrict__ Y,
                                                 const float* __restrict__ bias,
                                                 float* __restrict__ S) {
    __shared__ float sA0[64][65];
    __shared__ float sB0[64][65];
    __shared__ int   sLast;

    int tid = threadIdx.x;
    int tx = tid & 15;
    int ty = tid >> 4;
    int bid = blockIdx.x;

    if (bid < 128) {
        // ----------------- k2 producer path -----------------
        int ks    = bid & 3;
        int rtile = (bid >> 2) & 7;
        int etile = bid >> 5;            // 0..3
        int e0 = etile * 64;
        int r0 = rtile * 64;
        int kc = ks * 64;

#pragma unroll
        for (int t = 0; t < 4; t++) {
            int lin = tid + t * 256;
            int row = lin >> 4;
            int c4  = (lin & 15) << 2;
            float4 xv = *reinterpret_cast<const float4*>(&X[(r0 + row) * Dz + kc + c4]);
            sA0[row][c4 + 0] = xv.x; sA0[row][c4 + 1] = xv.y;
            sA0[row][c4 + 2] = xv.z; sA0[row][c4 + 3] = xv.w;
            float4 av = *reinterpret_cast<const float4*>(&g_Aw[(kc + row) * Dz + e0 + c4]);
            sB0[row][c4 + 0] = av.x; sB0[row][c4 + 1] = av.y;
            sB0[row][c4 + 2] = av.z; sB0[row][c4 + 3] = av.w;
        }
        __syncthreads();

        float acc[4][4] = {};
#pragma unroll 16
        for (int k = 0; k < 64; k++) {
            float xv[4], av[4];
#pragma unroll
            for (int i = 0; i < 4; i++) xv[i] = sA0[ty + 16 * i][k];
#pragma unroll
            for (int j = 0; j < 4; j++) av[j] = sB0[k][tx + 16 * j];
#pragma unroll
            for (int i = 0; i < 4; i++)
#pragma unroll
                for (int j = 0; j < 4; j++)
                    acc[i][j] += xv[i] * av[j];
        }

        float* out = g_Tp + (long)ks * TSZ;
#pragma unroll
        for (int i = 0; i < 4; i++)
#pragma unroll
            for (int j = 0; j < 4; j++)
                out[(r0 + ty + 16 * i) * Dz + e0 + tx + 16 * j] = acc[i][j];

        __threadfence();
        __syncthreads();
        if (tid == 0) atomicAdd(&g_cnt2[rtile * 4 + etile], 1);
        return;
    }

    // ----------------- k3 consumer path -----------------
    {
        int bid2 = bid - 128;            // 0..63
        int mt = bid2 & 1;
        int nt = (bid2 >> 1) & 1;
        int z  = bid2 >> 2;              // 0..15
        int b  = z >> 2;
        int ks = z & 3;
        int m0 = mt * 64;
        int n0 = nt * 64;
        int kc = ks * 64;                // e chunk
        int rtile = b * 2 + nt;          // 64-row tile of flattened (b,n)
        int gid = (b * 2 + nt) * 2 + mt; // 0..15 epilogue group

        // Wait for the 4 d-chunk producers of (rtile, e-chunk=ks)
        if (tid == 0)
            while (atomicAdd(&g_cnt2[rtile * 4 + ks], 0) < KSPLIT) { }
        __syncthreads();
        __threadfence();

        long tb = (long)b * Nz * Dz;
        const float* Yb = Y + (long)b * Mz * Dz;

#pragma unroll
        for (int t = 0; t < 4; t++) {
            int lin = tid + t * 256;
            int row = lin >> 4;
            int c4  = (lin & 15) << 2;
            long base = tb + (long)(n0 + row) * Dz + kc + c4;
            float4 t0 = *reinterpret_cast<const float4*>(&g_Tp[0 * TSZ + base]);
            float4 t1 = *reinterpret_cast<const float4*>(&g_Tp[1 * TSZ + base]);
            float4 t2 = *reinterpret_cast<const float4*>(&g_Tp[2 * TSZ + base]);
            float4 t3 = *reinterpret_cast<const float4*>(&g_Tp[3 * TSZ + base]);
            sA0[row][c4 + 0] = t0.x + t1.x + t2.x + t3.x;
            sA0[row][c4 + 1] = t0.y + t1.y + t2.y + t3.y;
            sA0[row][c4 + 2] = t0.z + t1.z + t2.z + t3.z;
            sA0[row][c4 + 3] = t0.w + t1.w + t2.w + t3.w;
            float4 yv = *reinterpret_cast<const float4*>(&Yb[(long)(m0 + row) * Dz + kc + c4]);
            sB0[row][c4 + 0] = yv.x; sB0[row][c4 + 1] = yv.y;
            sB0[row][c4 + 2] = yv.z; sB0[row][c4 + 3] = yv.w;
        }
        __syncthreads();

        float acc[4][4] = {};
#pragma unroll 16
        for (int e = 0; e < 64; e++) {
            float tv[4], yv[4];
#pragma unroll
            for (int i = 0; i < 4; i++) tv[i] = sA0[ty + 16 * i][e];
#pragma unroll
            for (int j = 0; j < 4; j++) yv[j] = sB0[tx + 16 * j][e];
#pragma unroll
            for (int i = 0; i < 4; i++)
#pragma unroll
                for (int j = 0; j < 4; j++)
                    acc[i][j] += tv[i] * yv[j];
        }

        long sbase = (long)b * Nz * Mz;
        float* out = g_Sp + (long)ks * SSZ + sbase;
#pragma unroll
        for (int i = 0; i < 4; i++)
#pragma unroll
            for (int j = 0; j < 4; j++)
                out[(n0 + ty + 16 * i) * Mz + m0 + tx + 16 * j] = acc[i][j];

        // Fused deterministic split-K reduction: last of the 4 ks blocks
        __threadfence();
        __syncthreads();
        if (tid == 0) sLast = (atomicAdd(&g_cnt3[gid], 1) == KSPLIT - 1);
        __syncthreads();
        if (sLast) {
            float bv = bias[0];
#pragma unroll
            for (int t = 0; t < 4; t++) {
                int lin = tid + t * 256;
                int row = lin >> 4;
                int c4  = (lin & 15) << 2;
                long p = sbase + (long)(n0 + row) * Mz + m0 + c4;
                float4 a0 = *reinterpret_cast<const float4*>(&g_Sp[0 * SSZ + p]);
                float4 a1 = *reinterpret_cast<const float4*>(&g_Sp[1 * SSZ + p]);
                float4 a2 = *reinterpret_cast<const float4*>(&g_Sp[2 * SSZ + p]);
                float4 a3 = *reinterpret_cast<const float4*>(&g_Sp[3 * SSZ + p]);
                float4 r;
                r.x = a0.x + a1.x + a2.x + a3.x + bv;
                r.y = a0.y + a1.y + a2.y + a3.y + bv;
                r.z = a0.z + a1.z + a2.z + a3.z + bv;
                r.w = a0.w + a1.w + a2.w + a3.w + bv;
                *reinterpret_cast<float4*>(&S[p]) = r;
            }
        }
    }
}

// ---------------------------------------------------------------------------
// Launch: inputs in order X, Y, A, W, b
// ---------------------------------------------------------------------------
extern "C" void kernel_launch(void* const* d_in, const int* in_sizes, int n_in,
                              void* d_out, int out_size) {
    const float* X = (const float*)d_in[0];  // [4,128,256]
    const float* Y = (const float*)d_in[1];  // [4,128,256]
    const float* A = (const float*)d_in[2];  // [256,256,1024]
    const float* W = (const float*)d_in[3];  // [1,1024]
    const float* b = (const float*)d_in[4];  // [1]
    float* S = (float*)d_out;                // [4,128,128]

    k1_reduce_A<<<8192, 256>>>(A, W);
    k23_fused<<<192, 256>>>(X, Y, b, S);
}